// round 1
// baseline (speedup 1.0000x reference)
#include <cuda_runtime.h>

// ============================================================================
// AdditiveAttention fused kernel for GB300 (sm_103a)
//   q = queries @ W_q            [8,256,128]
//   k = keys @ W_k               [8,1024,128]
//   scores[b,q,k] = sum_h w_v[h] * tanh(q[b,q,h] + k[b,k,h])
//   masked softmax over k (positions >= valid_len[b] -> exactly 0 weight)
//   out = attn @ values          [8,256,128]
// ============================================================================

#define NEG_FILL (-1e6f)

// Scratch for projected q/k (allocation-free: __device__ globals)
__device__ float g_qh[8 * 256 * 128];    // 1 MB
__device__ float g_kh[8 * 1024 * 128];   // 4 MB

__device__ __forceinline__ float fast_tanh(float x) {
    float y;
    asm("tanh.approx.f32 %0, %1;" : "=f"(y) : "f"(x));
    return y;
}

// ----------------------------------------------------------------------------
// Projection GEMM: Y[rows,128] = X[rows,256] @ W[256,128]
// One fused launch handles both projections (blocks 0..31 -> q, 32..159 -> k).
// BM=64, BN=128, BK=16, 256 threads, 4x8 register microtile per thread.
// ----------------------------------------------------------------------------
__global__ __launch_bounds__(256) void proj_kernel(
    const float* __restrict__ Xq, const float* __restrict__ Xk,
    const float* __restrict__ Wq, const float* __restrict__ Wk)
{
    const int NQBLK = (8 * 256) / 64;   // 32
    const float* X; const float* W; float* Y; int row0;
    if (blockIdx.x < NQBLK) {
        X = Xq; W = Wq; Y = g_qh; row0 = blockIdx.x * 64;
    } else {
        X = Xk; W = Wk; Y = g_kh; row0 = (blockIdx.x - NQBLK) * 64;
    }

    __shared__ float Xs[16][64];    // [k][row] (transposed)
    __shared__ float Ws[16][128];   // [k][col]

    int tid = threadIdx.x;
    int tx = tid & 15;      // 0..15 -> cols tx*8..tx*8+7
    int ty = tid >> 4;      // 0..15 -> rows ty*4..ty*4+3

    float acc[4][8];
#pragma unroll
    for (int i = 0; i < 4; i++)
#pragma unroll
        for (int j = 0; j < 8; j++) acc[i][j] = 0.f;

    for (int k0 = 0; k0 < 256; k0 += 16) {
        // Load X tile 64x16 (transposed into Xs)
        {
            int r = tid >> 2;             // 0..63
            int c = (tid & 3) << 2;       // 0,4,8,12
            float4 v = *(const float4*)&X[(row0 + r) * 256 + k0 + c];
            Xs[c + 0][r] = v.x; Xs[c + 1][r] = v.y;
            Xs[c + 2][r] = v.z; Xs[c + 3][r] = v.w;
        }
        // Load W tile 16x128
        {
            int r = tid >> 5;             // 0..7
            int c = (tid & 31) << 2;      // 0..124
            *(float4*)&Ws[r][c]     = *(const float4*)&W[(k0 + r) * 128 + c];
            *(float4*)&Ws[r + 8][c] = *(const float4*)&W[(k0 + r + 8) * 128 + c];
        }
        __syncthreads();
#pragma unroll
        for (int k = 0; k < 16; k++) {
            float4 a  = *(float4*)&Xs[k][ty * 4];
            float4 b0 = *(float4*)&Ws[k][tx * 8];
            float4 b1 = *(float4*)&Ws[k][tx * 8 + 4];
            float av[4] = {a.x, a.y, a.z, a.w};
            float bv[8] = {b0.x, b0.y, b0.z, b0.w, b1.x, b1.y, b1.z, b1.w};
#pragma unroll
            for (int i = 0; i < 4; i++)
#pragma unroll
                for (int j = 0; j < 8; j++)
                    acc[i][j] += av[i] * bv[j];
        }
        __syncthreads();
    }

#pragma unroll
    for (int i = 0; i < 4; i++) {
        int r = row0 + ty * 4 + i;
        float4 o0 = {acc[i][0], acc[i][1], acc[i][2], acc[i][3]};
        float4 o1 = {acc[i][4], acc[i][5], acc[i][6], acc[i][7]};
        *(float4*)&Y[r * 128 + tx * 8]     = o0;
        *(float4*)&Y[r * 128 + tx * 8 + 4] = o1;
    }
}

// ----------------------------------------------------------------------------
// Fused score + online-softmax + AV kernel.
// Block = (batch b, tile of QT=8 q-rows). 8 warps, warp-per-row, lane-per-k.
// K/V tiles of KT=32 rows staged in smem, rows padded to 132 floats so that
// per-lane LDS.128 reads (stride 528B) are bank-conflict-free per 8-lane phase.
// Tiles beyond valid_len[b] are skipped entirely (exact: exp underflows to 0).
// ----------------------------------------------------------------------------
#define QT 8
#define KT 32
#define KP 132

__global__ __launch_bounds__(256) void attn_kernel(
    const float* __restrict__ V, const int* __restrict__ valid_lens,
    const float* __restrict__ w_v, float* __restrict__ out)
{
    __shared__ float ks[KT][KP];       // 16896 B
    __shared__ float vs[KT][KP];       // 16896 B
    __shared__ float qs[QT][128];      // 4096 B
    __shared__ float wv[128];          // 512 B
    __shared__ float pbuf[QT][KT];     // 1024 B   (total 39424 B)

    int b    = blockIdx.y;
    int q0   = blockIdx.x * QT;
    int tid  = threadIdx.x;
    int w    = tid >> 5;
    int lane = tid & 31;
    int nv   = valid_lens[b];          // 1..1024

    // Stage q rows + w_v
    {
        int r = tid >> 5;              // 0..7
        int c = (lane) << 2;           // 0..124
        *(float4*)&qs[r][c] = *(const float4*)&g_qh[((b << 8) + q0 + r) * 128 + c];
    }
    if (tid < 128) wv[tid] = w_v[tid];
    __syncthreads();

    float  m = -3.0e38f;
    float  l = 0.f;
    float4 o = {0.f, 0.f, 0.f, 0.f};

    int ntiles = (nv + KT - 1) >> 5;
    for (int t = 0; t < ntiles; t++) {
        int kb = t << 5;
        // Cooperative load of K tile and V tile (32 x 128 each)
        {
            int r = tid >> 3;          // 0..31
            const float* gk = &g_kh[((b << 10) + kb + r) * 128];
            const float* gv = &V    [((b << 10) + kb + r) * 128];
#pragma unroll
            for (int j = 0; j < 4; j++) {
                int c = ((tid & 7) + (j << 3)) << 2;   // float offset, x16B aligned
                *(float4*)&ks[r][c] = *(const float4*)&gk[c];
                *(float4*)&vs[r][c] = *(const float4*)&gv[c];
            }
        }
        __syncthreads();

        // Score for k = kb + lane (row q0 + w)
        float s = 0.f;
#pragma unroll
        for (int h = 0; h < 128; h += 4) {
            float4 kv = *(float4*)&ks[lane][h];
            float4 qv = *(float4*)&qs[w][h];
            float4 w4 = *(float4*)&wv[h];
            s += fast_tanh(qv.x + kv.x) * w4.x;
            s += fast_tanh(qv.y + kv.y) * w4.y;
            s += fast_tanh(qv.z + kv.z) * w4.z;
            s += fast_tanh(qv.w + kv.w) * w4.w;
        }
        if (kb + lane >= nv) s = NEG_FILL;   // exp -> exactly 0

        // Online softmax update (warp-wide)
        float tm = s;
#pragma unroll
        for (int off = 16; off; off >>= 1)
            tm = fmaxf(tm, __shfl_xor_sync(0xffffffffu, tm, off));
        float mn    = fmaxf(m, tm);
        float scale = __expf(m - mn);        // 0 on first tile (m = -3e38)
        float p     = __expf(s - mn);
        float ps    = p;
#pragma unroll
        for (int off = 16; off; off >>= 1)
            ps += __shfl_xor_sync(0xffffffffu, ps, off);
        l = l * scale + ps;
        m = mn;
        o.x *= scale; o.y *= scale; o.z *= scale; o.w *= scale;

        pbuf[w][lane] = p;
        __syncwarp();

        // AV accumulation: lane owns v = lane*4 .. lane*4+3
#pragma unroll
        for (int k = 0; k < KT; k++) {
            float  pk = pbuf[w][k];
            float4 vv = *(float4*)&vs[k][lane << 2];
            o.x += pk * vv.x; o.y += pk * vv.y;
            o.z += pk * vv.z; o.w += pk * vv.w;
        }
        __syncthreads();   // protect ks/vs before next tile's load
    }

    float inv = 1.0f / l;
    o.x *= inv; o.y *= inv; o.z *= inv; o.w *= inv;
    *(float4*)&out[((b << 8) + q0 + w) * 128 + (lane << 2)] = o;
}

// ----------------------------------------------------------------------------
// Launch
// ----------------------------------------------------------------------------
extern "C" void kernel_launch(void* const* d_in, const int* in_sizes, int n_in,
                              void* d_out, int out_size)
{
    const float* queries    = (const float*)d_in[0];  // [8,256,256]
    const float* keys       = (const float*)d_in[1];  // [8,1024,256]
    const float* values     = (const float*)d_in[2];  // [8,1024,128]
    const int*   valid_lens = (const int*)  d_in[3];  // [8]
    const float* W_q        = (const float*)d_in[4];  // [256,128]
    const float* W_k        = (const float*)d_in[5];  // [256,128]
    const float* w_v        = (const float*)d_in[6];  // [128]
    float*       out        = (float*)d_out;          // [8,256,128]

    // Projections (160 blocks: 32 for q rows, 128 for k rows)
    proj_kernel<<<160, 256>>>(queries, keys, W_q, W_k);

    // Fused attention: grid (Q/QT, B) = (32, 8), 256 threads
    dim3 grid(256 / QT, 8);
    attn_kernel<<<grid, 256>>>(values, valid_lens, w_v, out);
}

// round 2
// speedup vs baseline: 1.3231x; 1.3231x over previous
#include <cuda_runtime.h>

// ============================================================================
// AdditiveAttention fused kernels for GB300 (sm_103a) — Round 2
//   q = queries @ W_q            [8,256,128]
//   k = keys @ W_k               [8,1024,128]   (rows >= valid_len skipped)
//   scores[b,q,k] = sum_h w_v[h] * tanh(q[b,q,h] + k[b,k,h])
//   softmax WITHOUT max-subtraction (scores bounded by sum|w_v| ~ 9)
//   split-K over key tiles (S=4), partial (sum p, sum p*V) combined at end
// ============================================================================

#define NEG_FILL (-1e6f)
#define S_SPLIT 4
#define QT 8
#define KT 32
#define KP 132

// Scratch (allocation-free: __device__ globals)
__device__ float g_qh[8 * 256 * 128];                 // 1 MB
__device__ float g_kh[8 * 1024 * 128];                // 4 MB
__device__ float g_po[S_SPLIT * 2048 * 128];          // 4 MB partial o
__device__ float g_pl[S_SPLIT * 2048];                // 32 KB partial l

__device__ __forceinline__ float fast_tanh(float x) {
    float y;
    asm("tanh.approx.f32 %0, %1;" : "=f"(y) : "f"(x));
    return y;
}

// ----------------------------------------------------------------------------
// Projection GEMM: Y[rows,128] = X[rows,256] @ W[256,128]
// blocks 0..31 -> q rows, blocks 32..159 -> k rows.
// k-row blocks entirely beyond valid_len[b] exit immediately (never read).
// ----------------------------------------------------------------------------
__global__ __launch_bounds__(256) void proj_kernel(
    const float* __restrict__ Xq, const float* __restrict__ Xk,
    const float* __restrict__ Wq, const float* __restrict__ Wk,
    const int* __restrict__ valid_lens)
{
    const int NQBLK = (8 * 256) / 64;   // 32
    const float* X; const float* W; float* Y; int row0;
    if (blockIdx.x < NQBLK) {
        X = Xq; W = Wq; Y = g_qh; row0 = blockIdx.x * 64;
    } else {
        int kb = blockIdx.x - NQBLK;        // 0..127, 16 blocks per batch
        int b  = kb >> 4;
        int local = (kb & 15) * 64;
        if (local >= valid_lens[b]) return; // rows never read downstream
        X = Xk; W = Wk; Y = g_kh; row0 = kb * 64;
    }

    __shared__ float Xs[16][64];    // [k][row] (transposed)
    __shared__ float Ws[16][128];   // [k][col]

    int tid = threadIdx.x;
    int tx = tid & 15;      // cols tx*8..tx*8+7
    int ty = tid >> 4;      // rows ty*4..ty*4+3

    float acc[4][8];
#pragma unroll
    for (int i = 0; i < 4; i++)
#pragma unroll
        for (int j = 0; j < 8; j++) acc[i][j] = 0.f;

    for (int k0 = 0; k0 < 256; k0 += 16) {
        {
            int r = tid >> 2;
            int c = (tid & 3) << 2;
            float4 v = *(const float4*)&X[(row0 + r) * 256 + k0 + c];
            Xs[c + 0][r] = v.x; Xs[c + 1][r] = v.y;
            Xs[c + 2][r] = v.z; Xs[c + 3][r] = v.w;
        }
        {
            int r = tid >> 5;
            int c = (tid & 31) << 2;
            *(float4*)&Ws[r][c]     = *(const float4*)&W[(k0 + r) * 128 + c];
            *(float4*)&Ws[r + 8][c] = *(const float4*)&W[(k0 + r + 8) * 128 + c];
        }
        __syncthreads();
#pragma unroll
        for (int k = 0; k < 16; k++) {
            float4 a  = *(float4*)&Xs[k][ty * 4];
            float4 b0 = *(float4*)&Ws[k][tx * 8];
            float4 b1 = *(float4*)&Ws[k][tx * 8 + 4];
            float av[4] = {a.x, a.y, a.z, a.w};
            float bv[8] = {b0.x, b0.y, b0.z, b0.w, b1.x, b1.y, b1.z, b1.w};
#pragma unroll
            for (int i = 0; i < 4; i++)
#pragma unroll
                for (int j = 0; j < 8; j++)
                    acc[i][j] += av[i] * bv[j];
        }
        __syncthreads();
    }

#pragma unroll
    for (int i = 0; i < 4; i++) {
        int r = row0 + ty * 4 + i;
        float4 o0 = {acc[i][0], acc[i][1], acc[i][2], acc[i][3]};
        float4 o1 = {acc[i][4], acc[i][5], acc[i][6], acc[i][7]};
        *(float4*)&Y[r * 128 + tx * 8]     = o0;
        *(float4*)&Y[r * 128 + tx * 8 + 4] = o1;
    }
}

// ----------------------------------------------------------------------------
// Split-K score + exp + AV partial kernel.
// grid = (Q/QT, B, S_SPLIT). Block = 256 threads (8 warps, warp-per-q-row).
// Split sp processes key tiles t = sp, sp+S, ... (< ceil(nv/32)) — balanced.
// No max subtraction: |score| <= sum|w_v| (~9), exp is safe in fp32.
// ----------------------------------------------------------------------------
__global__ __launch_bounds__(256) void attn_partial_kernel(
    const float* __restrict__ V, const int* __restrict__ valid_lens,
    const float* __restrict__ w_v)
{
    __shared__ float ks[KT][KP];       // 16896 B
    __shared__ float vs[KT][KP];       // 16896 B
    __shared__ float qs[QT][128];      // 4096 B
    __shared__ float wv[128];          // 512 B   (total 38400 B)

    int b    = blockIdx.y;
    int q0   = blockIdx.x * QT;
    int sp   = blockIdx.z;
    int tid  = threadIdx.x;
    int w    = tid >> 5;
    int lane = tid & 31;
    int nv   = valid_lens[b];          // 1..1024

    // Stage q rows + w_v
    {
        int r = tid >> 5;
        int c = lane << 2;
        *(float4*)&qs[r][c] = *(const float4*)&g_qh[((b << 8) + q0 + r) * 128 + c];
    }
    if (tid < 128) wv[tid] = w_v[tid];
    __syncthreads();

    float  l = 0.f;
    float4 o = {0.f, 0.f, 0.f, 0.f};

    int ntiles = (nv + KT - 1) >> 5;
    for (int t = sp; t < ntiles; t += S_SPLIT) {
        int kb = t << 5;
        // Cooperative load of K tile and V tile (32 x 128 each)
        {
            int r = tid >> 3;
            const float* gk = &g_kh[((b << 10) + kb + r) * 128];
            const float* gv = &V    [((b << 10) + kb + r) * 128];
#pragma unroll
            for (int j = 0; j < 4; j++) {
                int c = ((tid & 7) + (j << 3)) << 2;
                *(float4*)&ks[r][c] = *(const float4*)&gk[c];
                *(float4*)&vs[r][c] = *(const float4*)&gv[c];
            }
        }
        __syncthreads();

        // Score for k = kb + lane (q row = q0 + w)
        float s = 0.f;
#pragma unroll
        for (int h = 0; h < 128; h += 4) {
            float4 kv = *(float4*)&ks[lane][h];
            float4 qv = *(float4*)&qs[w][h];
            float4 w4 = *(float4*)&wv[h];
            s += fast_tanh(qv.x + kv.x) * w4.x;
            s += fast_tanh(qv.y + kv.y) * w4.y;
            s += fast_tanh(qv.z + kv.z) * w4.z;
            s += fast_tanh(qv.w + kv.w) * w4.w;
        }
        if (kb + lane >= nv) s = NEG_FILL;   // exp -> exactly 0

        float p = __expf(s);
        l += p;

        // AV accumulation: lane owns output dims lane*4 .. lane*4+3
#pragma unroll
        for (int k = 0; k < KT; k++) {
            float  pk = __shfl_sync(0xffffffffu, p, k);
            float4 vv = *(float4*)&vs[k][lane << 2];
            o.x += pk * vv.x; o.y += pk * vv.y;
            o.z += pk * vv.z; o.w += pk * vv.w;
        }
        __syncthreads();   // protect ks/vs before next tile's load
    }

    // Reduce l across lanes (sum of this split's exp weights)
#pragma unroll
    for (int off = 16; off; off >>= 1)
        l += __shfl_xor_sync(0xffffffffu, l, off);

    int row = (b << 8) + q0 + w;
    if (lane == 0) g_pl[sp * 2048 + row] = l;
    *(float4*)&g_po[(sp * 2048 + row) * 128 + (lane << 2)] = o;
}

// ----------------------------------------------------------------------------
// Combine partials: out[row,:] = sum_s o_s / sum_s l_s
// ----------------------------------------------------------------------------
__global__ __launch_bounds__(256) void combine_kernel(float* __restrict__ out)
{
    int idx = blockIdx.x * 256 + threadIdx.x;   // 0 .. 65535
    int row = idx >> 5;
    int c   = (idx & 31) << 2;

    float  l = 0.f;
    float4 a = {0.f, 0.f, 0.f, 0.f};
#pragma unroll
    for (int s = 0; s < S_SPLIT; s++) {
        l += g_pl[s * 2048 + row];
        float4 v = *(const float4*)&g_po[(s * 2048 + row) * 128 + c];
        a.x += v.x; a.y += v.y; a.z += v.z; a.w += v.w;
    }
    float inv = 1.0f / l;
    a.x *= inv; a.y *= inv; a.z *= inv; a.w *= inv;
    *(float4*)&out[row * 128 + c] = a;
}

// ----------------------------------------------------------------------------
// Launch
// ----------------------------------------------------------------------------
extern "C" void kernel_launch(void* const* d_in, const int* in_sizes, int n_in,
                              void* d_out, int out_size)
{
    const float* queries    = (const float*)d_in[0];  // [8,256,256]
    const float* keys       = (const float*)d_in[1];  // [8,1024,256]
    const float* values     = (const float*)d_in[2];  // [8,1024,128]
    const int*   valid_lens = (const int*)  d_in[3];  // [8]
    const float* W_q        = (const float*)d_in[4];  // [256,128]
    const float* W_k        = (const float*)d_in[5];  // [256,128]
    const float* w_v        = (const float*)d_in[6];  // [128]
    float*       out        = (float*)d_out;          // [8,256,128]

    // Projections (160 blocks; k blocks beyond valid_len self-skip)
    proj_kernel<<<160, 256>>>(queries, keys, W_q, W_k, valid_lens);

    // Split-K attention partials: grid (32, 8, 4) = 1024 blocks
    dim3 grid(256 / QT, 8, S_SPLIT);
    attn_partial_kernel<<<grid, 256>>>(values, valid_lens, w_v);

    // Combine: 2048 rows x 128 dims / (256 threads * 4 floats) = 256 blocks
    combine_kernel<<<256, 256>>>(out);
}

// round 3
// speedup vs baseline: 1.4940x; 1.1291x over previous
#include <cuda_runtime.h>
#include <cstdint>

// ============================================================================
// AdditiveAttention fused kernels for GB300 (sm_103a) — Round 3
//   Pipelined proj GEMM (double-buffered smem, register prefetch)
//   Split-K attention with cp.async double-buffered K/V tiles (1 sync/tile)
// ============================================================================

#define NEG_FILL (-1e6f)
#define S_SPLIT 4
#define QT 8
#define KT 32
#define KP 132   // K-tile row pad: 132 % 8 == 4 -> conflict-free LDS.128 by lane

// Scratch (allocation-free: __device__ globals)
__device__ float g_qh[8 * 256 * 128];                 // 1 MB
__device__ float g_kh[8 * 1024 * 128];                // 4 MB
__device__ float g_po[S_SPLIT * 2048 * 128];          // 4 MB partial o
__device__ float g_pl[S_SPLIT * 2048];                // 32 KB partial l

__device__ __forceinline__ float fast_tanh(float x) {
    float y;
    asm("tanh.approx.f32 %0, %1;" : "=f"(y) : "f"(x));
    return y;
}

__device__ __forceinline__ void cp16(uint32_t s, const void* g) {
    asm volatile("cp.async.cg.shared.global [%0], [%1], 16;" :: "r"(s), "l"(g));
}
#define CP_COMMIT() asm volatile("cp.async.commit_group;")
#define CP_WAIT0()  asm volatile("cp.async.wait_group 0;")

// ----------------------------------------------------------------------------
// Projection GEMM: Y[rows,128] = X[rows,256] @ W[256,128]
// blocks 0..31 -> q rows, 32..159 -> k rows (blocks beyond valid_len skip).
// Double-buffered smem + register prefetch: LDG latency hidden under 512
// FFMAs/thread per k-step-group. One __syncthreads per iteration.
// ----------------------------------------------------------------------------
__global__ __launch_bounds__(256) void proj_kernel(
    const float* __restrict__ Xq, const float* __restrict__ Xk,
    const float* __restrict__ Wq, const float* __restrict__ Wk,
    const int* __restrict__ valid_lens)
{
    const int NQBLK = (8 * 256) / 64;   // 32
    const float* X; const float* W; float* Y; int row0;
    if (blockIdx.x < NQBLK) {
        X = Xq; W = Wq; Y = g_qh; row0 = blockIdx.x * 64;
    } else {
        int kb = blockIdx.x - NQBLK;        // 0..127, 16 per batch
        int b  = kb >> 4;
        if (((kb & 15) << 6) >= valid_lens[b]) return;  // never read downstream
        X = Xk; W = Wk; Y = g_kh; row0 = kb * 64;
    }

    __shared__ float Xs[2][16][64];     // [buf][k][row]
    __shared__ float Ws[2][16][128];    // [buf][k][col]   24 KB total

    int tid = threadIdx.x;
    int tx = tid & 15;      // cols tx*8..tx*8+7
    int ty = tid >> 4;      // rows ty*4..ty*4+3

    // load lane mapping
    int xr = tid >> 2;              // 0..63
    int xc = (tid & 3) << 2;        // 0,4,8,12
    int wr = tid >> 5;              // 0..7
    int wc = (tid & 31) << 2;       // 0..124

    const float* Xp = &X[(row0 + xr) * 256 + xc];
    const float* Wp0 = &W[wr * 128 + wc];
    const float* Wp1 = &W[(wr + 8) * 128 + wc];

    float acc[4][8];
#pragma unroll
    for (int i = 0; i < 4; i++)
#pragma unroll
        for (int j = 0; j < 8; j++) acc[i][j] = 0.f;

    // prologue: tile 0 -> buf 0
    float4 xv  = *(const float4*)Xp;
    float4 wv0 = *(const float4*)Wp0;
    float4 wv1 = *(const float4*)Wp1;
    Xs[0][xc + 0][xr] = xv.x; Xs[0][xc + 1][xr] = xv.y;
    Xs[0][xc + 2][xr] = xv.z; Xs[0][xc + 3][xr] = xv.w;
    *(float4*)&Ws[0][wr][wc]     = wv0;
    *(float4*)&Ws[0][wr + 8][wc] = wv1;
    __syncthreads();

    for (int it = 0; it < 16; it++) {
        int buf = it & 1;
        if (it < 15) {  // prefetch next tile into registers
            int k0 = (it + 1) << 4;
            xv  = *(const float4*)(Xp + k0);
            wv0 = *(const float4*)(Wp0 + k0 * 128);
            wv1 = *(const float4*)(Wp1 + k0 * 128);
        }
#pragma unroll
        for (int k = 0; k < 16; k++) {
            float4 a  = *(float4*)&Xs[buf][k][ty * 4];
            float4 b0 = *(float4*)&Ws[buf][k][tx * 8];
            float4 b1 = *(float4*)&Ws[buf][k][tx * 8 + 4];
            float av[4] = {a.x, a.y, a.z, a.w};
            float bv[8] = {b0.x, b0.y, b0.z, b0.w, b1.x, b1.y, b1.z, b1.w};
#pragma unroll
            for (int i = 0; i < 4; i++)
#pragma unroll
                for (int j = 0; j < 8; j++)
                    acc[i][j] += av[i] * bv[j];
        }
        if (it < 15) {  // stash prefetched tile into the other buffer
            int nb = buf ^ 1;
            Xs[nb][xc + 0][xr] = xv.x; Xs[nb][xc + 1][xr] = xv.y;
            Xs[nb][xc + 2][xr] = xv.z; Xs[nb][xc + 3][xr] = xv.w;
            *(float4*)&Ws[nb][wr][wc]     = wv0;
            *(float4*)&Ws[nb][wr + 8][wc] = wv1;
        }
        __syncthreads();
    }

#pragma unroll
    for (int i = 0; i < 4; i++) {
        int r = row0 + ty * 4 + i;
        float4 o0 = {acc[i][0], acc[i][1], acc[i][2], acc[i][3]};
        float4 o1 = {acc[i][4], acc[i][5], acc[i][6], acc[i][7]};
        *(float4*)&Y[r * 128 + tx * 8]     = o0;
        *(float4*)&Y[r * 128 + tx * 8 + 4] = o1;
    }
}

// ----------------------------------------------------------------------------
// Split-K score + exp + AV partial kernel, cp.async double-buffered.
// grid = (Q/QT, B, S_SPLIT), 256 threads (8 warps, warp-per-q-row, lane-per-k).
// Per tile: wait_group 0 -> sync -> issue next tile's cp.async -> compute.
// Dynamic smem layout (floats):
//   ks[2][32][132] @ 0        (8448)
//   vs[2][32][128] @ 8448     (8192)
//   qs[8][128]     @ 16640    (1024)
//   wv[128]        @ 17664    (128)    total 17792 floats = 71168 B
// ----------------------------------------------------------------------------
#define ATTN_SMEM_BYTES 71168

__global__ __launch_bounds__(256) void attn_partial_kernel(
    const float* __restrict__ V, const int* __restrict__ valid_lens,
    const float* __restrict__ w_v)
{
    extern __shared__ float sm[];
    float* qs = sm + 16640;
    float* wv = sm + 17664;

    int b    = blockIdx.y;
    int q0   = blockIdx.x * QT;
    int sp   = blockIdx.z;
    int tid  = threadIdx.x;
    int w    = tid >> 5;
    int lane = tid & 31;
    int nv   = valid_lens[b];          // 1..1024
    int ntiles = (nv + 31) >> 5;

    uint32_t su = (uint32_t)__cvta_generic_to_shared(sm);

    // tile-load lane mapping: 32 rows x 8 threads, 4 x 16B chunks per thread
    int lr = tid >> 3;                 // 0..31
    int lc = (tid & 7) << 2;           // float col base
    const float* gkb = g_kh + ((size_t)(b << 10) + lr) * 128 + lc;
    const float* gvb = V    + ((size_t)(b << 10) + lr) * 128 + lc;
    uint32_t ku0 = su + (uint32_t)(lr * KP  + lc) * 4u;   // ks buf0
    uint32_t vu0 = su + (uint32_t)(8448 + lr * 128 + lc) * 4u;

    // prologue: issue tile sp into buf 0
    if (sp < ntiles) {
        const float* gk = gkb + (sp << 5) * 128;
        const float* gv = gvb + (sp << 5) * 128;
#pragma unroll
        for (int j = 0; j < 4; j++) {
            cp16(ku0 + j * 128u, gk + (j << 3) * 4);
            cp16(vu0 + j * 128u, gv + (j << 3) * 4);
        }
    }
    CP_COMMIT();

    // stage q rows + w_v (overlaps with cp.async)
    {
        int r = tid >> 5;
        int c = lane << 2;
        *(float4*)&qs[r * 128 + c] =
            *(const float4*)&g_qh[((b << 8) + q0 + r) * 128 + c];
    }
    if (tid < 128) wv[tid] = w_v[tid];

    float  l = 0.f;
    float4 o = {0.f, 0.f, 0.f, 0.f};

    int buf = 0;
    for (int t = sp; t < ntiles; t += S_SPLIT, buf ^= 1) {
        CP_WAIT0();          // current tile's group is the only one pending
        __syncthreads();     // visibility for all + prior buffer reads done

        int tn = t + S_SPLIT;
        if (tn < ntiles) {   // issue next tile into the other buffer
            uint32_t off = (buf ^ 1) ? 0x4200u /*4224*4*/ : 0u;
            uint32_t voff = (buf ^ 1) ? 0x4000u /*4096*4*/ : 0u;
            const float* gk = gkb + (tn << 5) * 128;
            const float* gv = gvb + (tn << 5) * 128;
#pragma unroll
            for (int j = 0; j < 4; j++) {
                cp16(ku0 + off  + j * 128u, gk + (j << 3) * 4);
                cp16(vu0 + voff + j * 128u, gv + (j << 3) * 4);
            }
        }
        CP_COMMIT();

        // ---- score for k = (t<<5) + lane, q row q0 + w ----
        const float* ksp = sm + buf * 4224 + lane * KP;
        const float* qsp = qs + w * 128;
        float s = 0.f;
#pragma unroll
        for (int h = 0; h < 128; h += 4) {
            float4 kv = *(float4*)&ksp[h];
            float4 qv = *(float4*)&qsp[h];
            float4 w4 = *(float4*)&wv[h];
            s += fast_tanh(qv.x + kv.x) * w4.x;
            s += fast_tanh(qv.y + kv.y) * w4.y;
            s += fast_tanh(qv.z + kv.z) * w4.z;
            s += fast_tanh(qv.w + kv.w) * w4.w;
        }
        if ((t << 5) + lane >= nv) s = NEG_FILL;   // exp -> exactly 0

        float p = __expf(s);
        l += p;

        // ---- AV: lane owns output dims lane*4 .. lane*4+3 ----
        const float* vsp = sm + 8448 + buf * 4096;
#pragma unroll
        for (int k = 0; k < KT; k++) {
            float  pk = __shfl_sync(0xffffffffu, p, k);
            float4 vv = *(float4*)&vsp[k * 128 + (lane << 2)];
            o.x += pk * vv.x; o.y += pk * vv.y;
            o.z += pk * vv.z; o.w += pk * vv.w;
        }
    }

    // reduce l across lanes
#pragma unroll
    for (int off = 16; off; off >>= 1)
        l += __shfl_xor_sync(0xffffffffu, l, off);

    int row = (b << 8) + q0 + w;
    if (lane == 0) g_pl[sp * 2048 + row] = l;
    *(float4*)&g_po[(sp * 2048 + row) * 128 + (lane << 2)] = o;
}

// ----------------------------------------------------------------------------
// Combine partials: out[row,:] = sum_s o_s / sum_s l_s
// ----------------------------------------------------------------------------
__global__ __launch_bounds__(256) void combine_kernel(float* __restrict__ out)
{
    int idx = blockIdx.x * 256 + threadIdx.x;   // 0 .. 65535
    int row = idx >> 5;
    int c   = (idx & 31) << 2;

    float  l = 0.f;
    float4 a = {0.f, 0.f, 0.f, 0.f};
#pragma unroll
    for (int s = 0; s < S_SPLIT; s++) {
        l += g_pl[s * 2048 + row];
        float4 v = *(const float4*)&g_po[(s * 2048 + row) * 128 + c];
        a.x += v.x; a.y += v.y; a.z += v.z; a.w += v.w;
    }
    float inv = 1.0f / l;
    a.x *= inv; a.y *= inv; a.z *= inv; a.w *= inv;
    *(float4*)&out[row * 128 + c] = a;
}

// ----------------------------------------------------------------------------
// Launch
// ----------------------------------------------------------------------------
extern "C" void kernel_launch(void* const* d_in, const int* in_sizes, int n_in,
                              void* d_out, int out_size)
{
    const float* queries    = (const float*)d_in[0];  // [8,256,256]
    const float* keys       = (const float*)d_in[1];  // [8,1024,256]
    const float* values     = (const float*)d_in[2];  // [8,1024,128]
    const int*   valid_lens = (const int*)  d_in[3];  // [8]
    const float* W_q        = (const float*)d_in[4];  // [256,128]
    const float* W_k        = (const float*)d_in[5];  // [256,128]
    const float* w_v        = (const float*)d_in[6];  // [128]
    float*       out        = (float*)d_out;          // [8,256,128]

    // allow >48KB dynamic smem for the attention kernel (idempotent)
    cudaFuncSetAttribute(attn_partial_kernel,
                         cudaFuncAttributeMaxDynamicSharedMemorySize,
                         ATTN_SMEM_BYTES);

    proj_kernel<<<160, 256>>>(queries, keys, W_q, W_k, valid_lens);

    dim3 grid(256 / QT, 8, S_SPLIT);
    attn_partial_kernel<<<grid, 256, ATTN_SMEM_BYTES>>>(values, valid_lens, w_v);

    combine_kernel<<<256, 256>>>(out);
}